// round 5
// baseline (speedup 1.0000x reference)
#include <cuda_runtime.h>
#include <cuda_bf16.h>
#include <cstdint>

#define Bn 16
#define Tn 2048
#define Cn 1024
#define Hn 64
#define LD 72          // smem row stride for 64-wide bf16 tiles
#define LD2 136        // smem row stride for 128-wide bf16 tiles

// ---------------- static scratch ----------------
__device__ __nv_bfloat16 g_qh[(size_t)Bn * Tn * Hn];
__device__ __nv_bfloat16 g_ql[(size_t)Bn * Tn * Hn];
__device__ __nv_bfloat16 g_kh[(size_t)Bn * Tn * Hn];
__device__ __nv_bfloat16 g_kl[(size_t)Bn * Tn * Hn];
__device__ __nv_bfloat16 g_vh[(size_t)Bn * Hn * Tn];   // transposed [b][d][t]
__device__ __nv_bfloat16 g_vl[(size_t)Bn * Hn * Tn];
__device__ float g_z[(size_t)Bn * 16 * Tn];            // per-(b,bt) column sumexp
__device__ float g_sc[Bn * Tn];                        // 1 / sum_bt z

// ---------------- helpers ----------------
__device__ __forceinline__ uint32_t smem_u32(const void* p) {
    uint32_t a;
    asm("{ .reg .u64 t; cvta.to.shared.u64 t, %1; cvt.u32.u64 %0, t; }" : "=r"(a) : "l"(p));
    return a;
}
__device__ __forceinline__ void ldsm_x4(uint32_t& r0, uint32_t& r1, uint32_t& r2, uint32_t& r3, uint32_t a) {
    asm volatile("ldmatrix.sync.aligned.m8n8.x4.shared.b16 {%0,%1,%2,%3}, [%4];"
                 : "=r"(r0), "=r"(r1), "=r"(r2), "=r"(r3) : "r"(a));
}
__device__ __forceinline__ void mma_bf16(float* c, uint32_t a0, uint32_t a1, uint32_t a2, uint32_t a3,
                                         uint32_t b0, uint32_t b1) {
    asm volatile("mma.sync.aligned.m16n8k16.row.col.f32.bf16.bf16.f32 "
                 "{%0,%1,%2,%3},{%4,%5,%6,%7},{%8,%9},{%0,%1,%2,%3};"
                 : "+f"(c[0]), "+f"(c[1]), "+f"(c[2]), "+f"(c[3])
                 : "r"(a0), "r"(a1), "r"(a2), "r"(a3), "r"(b0), "r"(b1));
}
__device__ __forceinline__ uint32_t pack_bf2(__nv_bfloat16 a, __nv_bfloat16 b) {
    unsigned short ua = *reinterpret_cast<unsigned short*>(&a);
    unsigned short ub = *reinterpret_cast<unsigned short*>(&b);
    return ((uint32_t)ub << 16) | ua;
}
__device__ __forceinline__ float fast_exp(float x) {
    float y = fmaxf(x * 1.4426950408889634f, -126.0f);
    float z = y + 12582912.0f;
    int   i = __float_as_int(z) - 0x4B400000;
    float f = y - (z - 12582912.0f);
    float p = 1.3333558146428443e-3f;
    p = fmaf(p, f, 9.618129107628477e-3f);
    p = fmaf(p, f, 5.550410866482158e-2f);
    p = fmaf(p, f, 2.402265069591007e-1f);
    p = fmaf(p, f, 6.931471805599453e-1f);
    p = fmaf(p, f, 1.0f);
    return __int_as_float(__float_as_int(p) + (i << 23));
}
__device__ __forceinline__ void split2(float v, __nv_bfloat16& h, __nv_bfloat16& l) {
    h = __float2bfloat16(v);
    l = __float2bfloat16(v - __bfloat162float(h));
}

// ================= K1: QKV projection (unchanged, verified) =================
#define QK_SMEM ((128 * LD + 128 * LD + 64 * LD + 64 * LD) * 2)
__global__ __launch_bounds__(256) void qkv_kernel(
    const float* __restrict__ x,
    const float* __restrict__ Wq, const float* __restrict__ bq,
    const float* __restrict__ Wk, const float* __restrict__ bk,
    const float* __restrict__ Wv, const float* __restrict__ bv)
{
    extern __shared__ char sm[];
    __nv_bfloat16* Ah = (__nv_bfloat16*)sm;
    __nv_bfloat16* Al = Ah + 128 * LD;
    __nv_bfloat16* Bh = Al + 128 * LD;
    __nv_bfloat16* Bl = Bh + 64 * LD;
    const int tid = threadIdx.x, lane = tid & 31, wid = tid >> 5;
    const int wm = wid & 3, wn = wid >> 2;
    const int mb = blockIdx.x * 128;
    const int mat = blockIdx.y;
    const float* W  = (mat == 0) ? Wq : (mat == 1) ? Wk : Wv;
    const float* bp = (mat == 0) ? bq : (mat == 1) ? bk : bv;

    const uint32_t sAh = smem_u32(Ah), sAl = smem_u32(Al);
    const uint32_t sBh = smem_u32(Bh), sBl = smem_u32(Bl);
    const int lr = lane & 15, lc = (lane & 16) >> 1;
    const int br = (lane & 7) + ((lane & 16) >> 1), bc = lane & 8;

    float acc[2][4][4];
    #pragma unroll
    for (int m = 0; m < 2; m++)
        #pragma unroll
        for (int j = 0; j < 4; j++)
            #pragma unroll
            for (int e = 0; e < 4; e++) acc[m][j][e] = 0.0f;

    for (int ch = 0; ch < 16; ch++) {
        const int k0c = ch * 64;
        #pragma unroll
        for (int i = 0; i < 8; i++) {
            int idx = tid + i * 256;
            int row = idx >> 4, c4 = (idx & 15) * 4;
            float4 v = *(const float4*)(x + (size_t)(mb + row) * Cn + k0c + c4);
            __nv_bfloat16 h, l;
            split2(v.x, h, l); Ah[row * LD + c4]     = h; Al[row * LD + c4]     = l;
            split2(v.y, h, l); Ah[row * LD + c4 + 1] = h; Al[row * LD + c4 + 1] = l;
            split2(v.z, h, l); Ah[row * LD + c4 + 2] = h; Al[row * LD + c4 + 2] = l;
            split2(v.w, h, l); Ah[row * LD + c4 + 3] = h; Al[row * LD + c4 + 3] = l;
        }
        #pragma unroll
        for (int i = 0; i < 4; i++) {
            int idx = tid + i * 256;
            int k = idx >> 4, n4 = (idx & 15) * 4;
            float4 w = *(const float4*)(W + (size_t)(k0c + k) * Hn + n4);
            __nv_bfloat16 h, l;
            split2(w.x, h, l); Bh[(n4)     * LD + k] = h; Bl[(n4)     * LD + k] = l;
            split2(w.y, h, l); Bh[(n4 + 1) * LD + k] = h; Bl[(n4 + 1) * LD + k] = l;
            split2(w.z, h, l); Bh[(n4 + 2) * LD + k] = h; Bl[(n4 + 2) * LD + k] = l;
            split2(w.w, h, l); Bh[(n4 + 3) * LD + k] = h; Bl[(n4 + 3) * LD + k] = l;
        }
        __syncthreads();
        #pragma unroll
        for (int ks = 0; ks < 4; ks++) {
            const int k0 = ks * 16;
            uint32_t ah[2][4], al[2][4], bh[2][4], bl[2][4];
            #pragma unroll
            for (int m = 0; m < 2; m++) {
                uint32_t ra = (uint32_t)(((wm * 32 + m * 16 + lr) * LD + k0 + lc) * 2);
                ldsm_x4(ah[m][0], ah[m][1], ah[m][2], ah[m][3], sAh + ra);
                ldsm_x4(al[m][0], al[m][1], al[m][2], al[m][3], sAl + ra);
            }
            #pragma unroll
            for (int g = 0; g < 2; g++) {
                uint32_t rb = (uint32_t)(((wn * 32 + g * 16 + br) * LD + k0 + bc) * 2);
                ldsm_x4(bh[g][0], bh[g][1], bh[g][2], bh[g][3], sBh + rb);
                ldsm_x4(bl[g][0], bl[g][1], bl[g][2], bl[g][3], sBl + rb);
            }
            #pragma unroll
            for (int m = 0; m < 2; m++)
                #pragma unroll
                for (int j = 0; j < 4; j++) {
                    uint32_t b0h = bh[j >> 1][(j & 1) * 2], b1h = bh[j >> 1][(j & 1) * 2 + 1];
                    uint32_t b0l = bl[j >> 1][(j & 1) * 2], b1l = bl[j >> 1][(j & 1) * 2 + 1];
                    mma_bf16(acc[m][j], ah[m][0], ah[m][1], ah[m][2], ah[m][3], b0h, b1h);
                    mma_bf16(acc[m][j], al[m][0], al[m][1], al[m][2], al[m][3], b0h, b1h);
                    mma_bf16(acc[m][j], ah[m][0], ah[m][1], ah[m][2], ah[m][3], b0l, b1l);
                }
        }
        __syncthreads();
    }

    const int quad = lane >> 2, pair = lane & 3;
    const int b = mb >> 11, tloc0 = mb & 2047;
    if (mat < 2) {
        uint32_t* dh = (uint32_t*)(mat == 0 ? g_qh : g_kh);
        uint32_t* dl = (uint32_t*)(mat == 0 ? g_ql : g_kl);
        #pragma unroll
        for (int m = 0; m < 2; m++)
            #pragma unroll
            for (int rr = 0; rr < 2; rr++)
                #pragma unroll
                for (int j = 0; j < 4; j++) {
                    int row = wm * 32 + m * 16 + rr * 8 + quad;
                    int col = wn * 32 + j * 8 + 2 * pair;
                    float v0 = acc[m][j][rr * 2]     + bp[col];
                    float v1 = acc[m][j][rr * 2 + 1] + bp[col + 1];
                    __nv_bfloat16 h0, l0, h1, l1;
                    split2(v0, h0, l0); split2(v1, h1, l1);
                    size_t o = (size_t)(mb + row) * 32 + (col >> 1);
                    dh[o] = pack_bf2(h0, h1);
                    dl[o] = pack_bf2(l0, l1);
                }
    } else {
        __nv_bfloat16* Th = Ah;
        __nv_bfloat16* Tl = Al;
        #pragma unroll
        for (int m = 0; m < 2; m++)
            #pragma unroll
            for (int rr = 0; rr < 2; rr++)
                #pragma unroll
                for (int j = 0; j < 4; j++) {
                    int row = wm * 32 + m * 16 + rr * 8 + quad;
                    int col = wn * 32 + j * 8 + 2 * pair;
                    float v0 = acc[m][j][rr * 2]     + bp[col];
                    float v1 = acc[m][j][rr * 2 + 1] + bp[col + 1];
                    __nv_bfloat16 h, l;
                    split2(v0, h, l); Th[col * 132 + row] = h; Tl[col * 132 + row] = l;
                    split2(v1, h, l); Th[(col + 1) * 132 + row] = h; Tl[(col + 1) * 132 + row] = l;
                }
        __syncthreads();
        uint32_t* vh32 = (uint32_t*)g_vh;
        uint32_t* vl32 = (uint32_t*)g_vl;
        const uint32_t* th32 = (const uint32_t*)Th;
        const uint32_t* tl32 = (const uint32_t*)Tl;
        #pragma unroll
        for (int i = 0; i < 16; i++) {
            int idx = tid + i * 256;
            int d = idx >> 6, t2 = idx & 63;
            size_t o = (size_t)(b * 64 + d) * 1024 + (tloc0 >> 1) + t2;
            vh32[o] = th32[d * 66 + t2];
            vl32[o] = tl32[d * 66 + t2];
        }
    }
}

// ================= pass1: S tile -> column sumexp z =================
#define P1_SMEM ((4 * 128 * LD) * 2 + 4 * 128 * 4)
__global__ __launch_bounds__(256) void pass1_kernel()
{
    const int bt = blockIdx.x, bs = blockIdx.y, b = blockIdx.z;
    if (bt < bs) return;
    extern __shared__ char sm[];
    __nv_bfloat16* Qh = (__nv_bfloat16*)sm;
    __nv_bfloat16* Ql = Qh + 128 * LD;
    __nv_bfloat16* Kh = Ql + 128 * LD;
    __nv_bfloat16* Kl = Kh + 128 * LD;
    float* zbuf = (float*)(Kl + 128 * LD);           // [4][128]

    const int tid = threadIdx.x, lane = tid & 31, wid = tid >> 5;
    const int wm = wid & 3, wn = wid >> 2;
    const int lr = lane & 15, lc = (lane & 16) >> 1;
    const int br = (lane & 7) + ((lane & 16) >> 1), bc = lane & 8;
    const int quad = lane >> 2, pair = lane & 3;

    {
        const uint4* qh = (const uint4*)(g_qh + ((size_t)b * Tn + bt * 128) * Hn);
        const uint4* ql = (const uint4*)(g_ql + ((size_t)b * Tn + bt * 128) * Hn);
        const uint4* kh = (const uint4*)(g_kh + ((size_t)b * Tn + bs * 128) * Hn);
        const uint4* kl = (const uint4*)(g_kl + ((size_t)b * Tn + bs * 128) * Hn);
        #pragma unroll
        for (int i = 0; i < 4; i++) {
            int idx = tid + i * 256;
            int row = idx >> 3, u = idx & 7;
            *(uint4*)&Qh[row * LD + u * 8] = qh[idx];
            *(uint4*)&Ql[row * LD + u * 8] = ql[idx];
            *(uint4*)&Kh[row * LD + u * 8] = kh[idx];
            *(uint4*)&Kl[row * LD + u * 8] = kl[idx];
        }
    }
    __syncthreads();

    const uint32_t sQh = smem_u32(Qh), sQl = smem_u32(Ql);
    const uint32_t sKh = smem_u32(Kh), sKl = smem_u32(Kl);

    float acc[2][8][4];
    #pragma unroll
    for (int m = 0; m < 2; m++)
        #pragma unroll
        for (int j = 0; j < 8; j++)
            #pragma unroll
            for (int e = 0; e < 4; e++) acc[m][j][e] = 0.0f;

    #pragma unroll
    for (int ks = 0; ks < 4; ks++) {
        const int k0 = ks * 16;
        uint32_t ah[2][4], al[2][4], bh[4][4], bl[4][4];
        #pragma unroll
        for (int m = 0; m < 2; m++) {
            uint32_t ra = (uint32_t)(((wm * 32 + m * 16 + lr) * LD + k0 + lc) * 2);
            ldsm_x4(ah[m][0], ah[m][1], ah[m][2], ah[m][3], sQh + ra);
            ldsm_x4(al[m][0], al[m][1], al[m][2], al[m][3], sQl + ra);
        }
        #pragma unroll
        for (int g = 0; g < 4; g++) {
            uint32_t rb = (uint32_t)(((wn * 64 + g * 16 + br) * LD + k0 + bc) * 2);
            ldsm_x4(bh[g][0], bh[g][1], bh[g][2], bh[g][3], sKh + rb);
            ldsm_x4(bl[g][0], bl[g][1], bl[g][2], bl[g][3], sKl + rb);
        }
        #pragma unroll
        for (int m = 0; m < 2; m++)
            #pragma unroll
            for (int j = 0; j < 8; j++) {
                uint32_t b0h = bh[j >> 1][(j & 1) * 2], b1h = bh[j >> 1][(j & 1) * 2 + 1];
                uint32_t b0l = bl[j >> 1][(j & 1) * 2], b1l = bl[j >> 1][(j & 1) * 2 + 1];
                mma_bf16(acc[m][j], ah[m][0], ah[m][1], ah[m][2], ah[m][3], b0h, b1h);
                mma_bf16(acc[m][j], al[m][0], al[m][1], al[m][2], al[m][3], b0h, b1h);
                mma_bf16(acc[m][j], ah[m][0], ah[m][1], ah[m][2], ah[m][3], b0l, b1l);
            }
    }

    #pragma unroll
    for (int j = 0; j < 8; j++) {
        float z0 = 0.0f, z1 = 0.0f;
        #pragma unroll
        for (int m = 0; m < 2; m++)
            #pragma unroll
            for (int rr = 0; rr < 2; rr++) {
                int trow = bt * 128 + wm * 32 + m * 16 + rr * 8 + quad;
                int scol = bs * 128 + wn * 64 + j * 8 + 2 * pair;
                z0 += (scol     <= trow) ? fast_exp(acc[m][j][rr * 2])     : 0.0f;
                z1 += (scol + 1 <= trow) ? fast_exp(acc[m][j][rr * 2 + 1]) : 0.0f;
            }
        #pragma unroll
        for (int off = 4; off < 32; off <<= 1) {
            z0 += __shfl_xor_sync(0xffffffffu, z0, off);
            z1 += __shfl_xor_sync(0xffffffffu, z1, off);
        }
        if (quad == 0) {
            int colloc = wn * 64 + j * 8 + 2 * pair;
            zbuf[wm * 128 + colloc]     = z0;
            zbuf[wm * 128 + colloc + 1] = z1;
        }
    }
    __syncthreads();
    if (tid < 128) {
        float z = zbuf[tid] + zbuf[128 + tid] + zbuf[256 + tid] + zbuf[384 + tid];
        g_z[((size_t)b * 16 + bt) * Tn + bs * 128 + tid] = z;
    }
}

// ================= cmerge: sc[b][s] = 1 / sum_bt z =================
__global__ __launch_bounds__(256) void cmerge_kernel()
{
    int idx = blockIdx.x * 256 + threadIdx.x;
    int b = idx >> 11, s = idx & 2047;
    float z = 0.0f;
    for (int bt = s >> 7; bt < 16; bt++)
        z += g_z[((size_t)b * 16 + bt) * Tn + s];
    g_sc[idx] = 1.0f / z;
}

// ================= pass2: fused S recompute + P*sc + P@V^T =================
#define P2_SMEM ((4 * 128 * LD + 2 * 128 * LD2 + 2 * 64 * LD2) * 2 + 512)
__global__ __launch_bounds__(256) void pass2_kernel(float* __restrict__ out)
{
    const int bt = 15 - blockIdx.x;
    const int b  = blockIdx.y;
    extern __shared__ char sm[];
    __nv_bfloat16* Qh = (__nv_bfloat16*)sm;          // [128][LD]
    __nv_bfloat16* Ql = Qh + 128 * LD;
    __nv_bfloat16* Kh = Ql + 128 * LD;
    __nv_bfloat16* Kl = Kh + 128 * LD;
    __nv_bfloat16* Ph = Kl + 128 * LD;               // [128][LD2]
    __nv_bfloat16* Pl = Ph + 128 * LD2;
    __nv_bfloat16* Vh = Pl + 128 * LD2;              // [64][LD2]
    __nv_bfloat16* Vl = Vh + 64 * LD2;
    float* cs = (float*)(Vl + 64 * LD2);             // [128]

    const int tid = threadIdx.x, lane = tid & 31, wid = tid >> 5;
    const int wm = wid & 3, wn = wid >> 2;
    const int lr = lane & 15, lc = (lane & 16) >> 1;
    const int br = (lane & 7) + ((lane & 16) >> 1), bc = lane & 8;
    const int quad = lane >> 2, pair = lane & 3;

    // load Q tile once
    {
        const uint4* qh = (const uint4*)(g_qh + ((size_t)b * Tn + bt * 128) * Hn);
        const uint4* ql = (const uint4*)(g_ql + ((size_t)b * Tn + bt * 128) * Hn);
        #pragma unroll
        for (int i = 0; i < 4; i++) {
            int idx = tid + i * 256;
            int row = idx >> 3, u = idx & 7;
            *(uint4*)&Qh[row * LD + u * 8] = qh[idx];
            *(uint4*)&Ql[row * LD + u * 8] = ql[idx];
        }
    }

    const uint32_t sQh = smem_u32(Qh), sQl = smem_u32(Ql);
    const uint32_t sKh = smem_u32(Kh), sKl = smem_u32(Kl);
    const uint32_t sPh = smem_u32(Ph), sPl = smem_u32(Pl);
    const uint32_t sVh = smem_u32(Vh), sVl = smem_u32(Vl);
    const uint4* gKh = (const uint4*)(g_kh + (size_t)b * Tn * Hn);
    const uint4* gKl = (const uint4*)(g_kl + (size_t)b * Tn * Hn);
    const uint4* gVh4 = (const uint4*)(g_vh + (size_t)b * Hn * Tn);
    const uint4* gVl4 = (const uint4*)(g_vl + (size_t)b * Hn * Tn);

    float accO[2][4][4];
    #pragma unroll
    for (int m = 0; m < 2; m++)
        #pragma unroll
        for (int j = 0; j < 4; j++)
            #pragma unroll
            for (int e = 0; e < 4; e++) accO[m][j][e] = 0.0f;

    for (int bs = 0; bs <= bt; bs++) {
        __syncthreads();   // prev iter's smem consumers done
        // K tile [128 s][64 k] hi/lo
        #pragma unroll
        for (int i = 0; i < 4; i++) {
            int idx = tid + i * 256;
            int row = idx >> 3, u = idx & 7;
            *(uint4*)&Kh[row * LD + u * 8] = gKh[bs * 1024 + idx];
            *(uint4*)&Kl[row * LD + u * 8] = gKl[bs * 1024 + idx];
        }
        // V^T tile [64 d][128 s] hi/lo
        #pragma unroll
        for (int i = 0; i < 4; i++) {
            int idx = tid + i * 256;
            int d = idx >> 4, c8 = idx & 15;
            *(uint4*)&Vh[d * LD2 + c8 * 8] = gVh4[(size_t)d * 256 + bs * 16 + c8];
            *(uint4*)&Vl[d * LD2 + c8 * 8] = gVl4[(size_t)d * 256 + bs * 16 + c8];
        }
        if (tid < 128) cs[tid] = g_sc[b * Tn + bs * 128 + tid];
        __syncthreads();

        // ---- S = Q K^T ----
        float acc[2][8][4];
        #pragma unroll
        for (int m = 0; m < 2; m++)
            #pragma unroll
            for (int j = 0; j < 8; j++)
                #pragma unroll
                for (int e = 0; e < 4; e++) acc[m][j][e] = 0.0f;
        #pragma unroll
        for (int ks = 0; ks < 4; ks++) {
            const int k0 = ks * 16;
            uint32_t ah[2][4], al[2][4], bh[4][4], bl[4][4];
            #pragma unroll
            for (int m = 0; m < 2; m++) {
                uint32_t ra = (uint32_t)(((wm * 32 + m * 16 + lr) * LD + k0 + lc) * 2);
                ldsm_x4(ah[m][0], ah[m][1], ah[m][2], ah[m][3], sQh + ra);
                ldsm_x4(al[m][0], al[m][1], al[m][2], al[m][3], sQl + ra);
            }
            #pragma unroll
            for (int g = 0; g < 4; g++) {
                uint32_t rb = (uint32_t)(((wn * 64 + g * 16 + br) * LD + k0 + bc) * 2);
                ldsm_x4(bh[g][0], bh[g][1], bh[g][2], bh[g][3], sKh + rb);
                ldsm_x4(bl[g][0], bl[g][1], bl[g][2], bl[g][3], sKl + rb);
            }
            #pragma unroll
            for (int m = 0; m < 2; m++)
                #pragma unroll
                for (int j = 0; j < 8; j++) {
                    uint32_t b0h = bh[j >> 1][(j & 1) * 2], b1h = bh[j >> 1][(j & 1) * 2 + 1];
                    uint32_t b0l = bl[j >> 1][(j & 1) * 2], b1l = bl[j >> 1][(j & 1) * 2 + 1];
                    mma_bf16(acc[m][j], ah[m][0], ah[m][1], ah[m][2], ah[m][3], b0h, b1h);
                    mma_bf16(acc[m][j], al[m][0], al[m][1], al[m][2], al[m][3], b0h, b1h);
                    mma_bf16(acc[m][j], ah[m][0], ah[m][1], ah[m][2], ah[m][3], b0l, b1l);
                }
        }

        // ---- P = exp(S) * sc, split, to smem ----
        #pragma unroll
        for (int j = 0; j < 8; j++)
            #pragma unroll
            for (int m = 0; m < 2; m++)
                #pragma unroll
                for (int rr = 0; rr < 2; rr++) {
                    int rloc = wm * 32 + m * 16 + rr * 8 + quad;
                    int cloc = wn * 64 + j * 8 + 2 * pair;
                    int trow = bt * 128 + rloc;
                    int scol = bs * 128 + cloc;
                    float p0 = (scol     <= trow) ? fast_exp(acc[m][j][rr * 2])     * cs[cloc]     : 0.0f;
                    float p1 = (scol + 1 <= trow) ? fast_exp(acc[m][j][rr * 2 + 1]) * cs[cloc + 1] : 0.0f;
                    __nv_bfloat16 h0, l0, h1, l1;
                    split2(p0, h0, l0); split2(p1, h1, l1);
                    *(uint32_t*)&Ph[rloc * LD2 + cloc] = pack_bf2(h0, h1);
                    *(uint32_t*)&Pl[rloc * LD2 + cloc] = pack_bf2(l0, l1);
                }
        __syncthreads();

        // ---- O += P @ V^T ----
        #pragma unroll
        for (int ks = 0; ks < 8; ks++) {
            const int k0 = ks * 16;
            uint32_t ah[2][4], al[2][4], bh[2][4], bl[2][4];
            #pragma unroll
            for (int m = 0; m < 2; m++) {
                uint32_t ra = (uint32_t)(((wm * 32 + m * 16 + lr) * LD2 + k0 + lc) * 2);
                ldsm_x4(ah[m][0], ah[m][1], ah[m][2], ah[m][3], sPh + ra);
                ldsm_x4(al[m][0], al[m][1], al[m][2], al[m][3], sPl + ra);
            }
            #pragma unroll
            for (int g = 0; g < 2; g++) {
                uint32_t rb = (uint32_t)(((wn * 32 + g * 16 + br) * LD2 + k0 + bc) * 2);
                ldsm_x4(bh[g][0], bh[g][1], bh[g][2], bh[g][3], sVh + rb);
                ldsm_x4(bl[g][0], bl[g][1], bl[g][2], bl[g][3], sVl + rb);
            }
            #pragma unroll
            for (int m = 0; m < 2; m++)
                #pragma unroll
                for (int j = 0; j < 4; j++) {
                    uint32_t b0h = bh[j >> 1][(j & 1) * 2], b1h = bh[j >> 1][(j & 1) * 2 + 1];
                    uint32_t b0l = bl[j >> 1][(j & 1) * 2], b1l = bl[j >> 1][(j & 1) * 2 + 1];
                    mma_bf16(accO[m][j], ah[m][0], ah[m][1], ah[m][2], ah[m][3], b0h, b1h);
                    mma_bf16(accO[m][j], al[m][0], al[m][1], al[m][2], al[m][3], b0h, b1h);
                    mma_bf16(accO[m][j], ah[m][0], ah[m][1], ah[m][2], ah[m][3], b0l, b1l);
                }
        }
    }

    #pragma unroll
    for (int m = 0; m < 2; m++)
        #pragma unroll
        for (int rr = 0; rr < 2; rr++)
            #pragma unroll
            for (int j = 0; j < 4; j++) {
                int row = bt * 128 + wm * 32 + m * 16 + rr * 8 + quad;
                int col = wn * 32 + j * 8 + 2 * pair;
                float2 v = make_float2(accO[m][j][rr * 2], accO[m][j][rr * 2 + 1]);
                *(float2*)(out + ((size_t)b * Tn + row) * Hn + col) = v;
            }
}

extern "C" void kernel_launch(void* const* d_in, const int* in_sizes, int n_in,
                              void* d_out, int out_size)
{
    const float* x  = (const float*)d_in[0];
    const float* Wq = (const float*)d_in[1];
    const float* bq = (const float*)d_in[2];
    const float* Wk = (const float*)d_in[3];
    const float* bk = (const float*)d_in[4];
    const float* Wv = (const float*)d_in[5];
    const float* bv = (const float*)d_in[6];
    float* out = (float*)d_out;

    cudaFuncSetAttribute(qkv_kernel,   cudaFuncAttributeMaxDynamicSharedMemorySize, QK_SMEM);
    cudaFuncSetAttribute(pass1_kernel, cudaFuncAttributeMaxDynamicSharedMemorySize, P1_SMEM);
    cudaFuncSetAttribute(pass2_kernel, cudaFuncAttributeMaxDynamicSharedMemorySize, P2_SMEM);

    qkv_kernel<<<dim3(256, 3), 256, QK_SMEM>>>(x, Wq, bq, Wk, bk, Wv, bv);
    pass1_kernel<<<dim3(16, 16, 16), 256, P1_SMEM>>>();
    cmerge_kernel<<<128, 256>>>();
    pass2_kernel<<<dim3(16, 16), 256, P2_SMEM>>>(out);
}

// round 7
// speedup vs baseline: 1.0871x; 1.0871x over previous
#include <cuda_runtime.h>
#include <cuda_bf16.h>
#include <cstdint>

#define Bn 16
#define Tn 2048
#define Cn 1024
#define Hn 64
#define LD 72          // padded stride used only by qkv kernel

// ---------------- static scratch ----------------
__device__ __nv_bfloat16 g_qh[(size_t)Bn * Tn * Hn];
__device__ __nv_bfloat16 g_ql[(size_t)Bn * Tn * Hn];
__device__ __nv_bfloat16 g_kh[(size_t)Bn * Tn * Hn];
__device__ __nv_bfloat16 g_kl[(size_t)Bn * Tn * Hn];
__device__ __nv_bfloat16 g_vh[(size_t)Bn * Hn * Tn];   // transposed [b][d][t]
__device__ __nv_bfloat16 g_vl[(size_t)Bn * Hn * Tn];
__device__ float g_z[(size_t)Bn * 32 * Tn];            // per-(b, 64-row tile) column sumexp
__device__ float g_sc[Bn * Tn];                        // 1 / sum z

// ---------------- helpers ----------------
__device__ __forceinline__ uint32_t smem_u32(const void* p) {
    uint32_t a;
    asm("{ .reg .u64 t; cvta.to.shared.u64 t, %1; cvt.u32.u64 %0, t; }" : "=r"(a) : "l"(p));
    return a;
}
__device__ __forceinline__ void ldsm_x4(uint32_t& r0, uint32_t& r1, uint32_t& r2, uint32_t& r3, uint32_t a) {
    asm volatile("ldmatrix.sync.aligned.m8n8.x4.shared.b16 {%0,%1,%2,%3}, [%4];"
                 : "=r"(r0), "=r"(r1), "=r"(r2), "=r"(r3) : "r"(a));
}
__device__ __forceinline__ void mma_bf16(float* c, uint32_t a0, uint32_t a1, uint32_t a2, uint32_t a3,
                                         uint32_t b0, uint32_t b1) {
    asm volatile("mma.sync.aligned.m16n8k16.row.col.f32.bf16.bf16.f32 "
                 "{%0,%1,%2,%3},{%4,%5,%6,%7},{%8,%9},{%0,%1,%2,%3};"
                 : "+f"(c[0]), "+f"(c[1]), "+f"(c[2]), "+f"(c[3])
                 : "r"(a0), "r"(a1), "r"(a2), "r"(a3), "r"(b0), "r"(b1));
}
__device__ __forceinline__ uint32_t pack_bf2(__nv_bfloat16 a, __nv_bfloat16 b) {
    unsigned short ua = *reinterpret_cast<unsigned short*>(&a);
    unsigned short ub = *reinterpret_cast<unsigned short*>(&b);
    return ((uint32_t)ub << 16) | ua;
}
__device__ __forceinline__ float fast_exp(float x) {
    float y = fmaxf(x * 1.4426950408889634f, -126.0f);
    float z = y + 12582912.0f;
    int   i = __float_as_int(z) - 0x4B400000;
    float f = y - (z - 12582912.0f);
    float p = 1.3333558146428443e-3f;
    p = fmaf(p, f, 9.618129107628477e-3f);
    p = fmaf(p, f, 5.550410866482158e-2f);
    p = fmaf(p, f, 2.402265069591007e-1f);
    p = fmaf(p, f, 6.931471805599453e-1f);
    p = fmaf(p, f, 1.0f);
    return __int_as_float(__float_as_int(p) + (i << 23));
}
__device__ __forceinline__ void split2(float v, __nv_bfloat16& h, __nv_bfloat16& l) {
    h = __float2bfloat16(v);
    l = __float2bfloat16(v - __bfloat162float(h));
}
// XOR swizzles (16B-unit granularity)
#define SW128(o) ((o) ^ (((o) >> 3) & 0x70))   // 128B rows
#define SW256(o) ((o) ^ (((o) >> 4) & 0x70))   // 256B rows

// ================= K1: QKV projection (unchanged, verified) =================
#define QK_SMEM ((128 * LD + 128 * LD + 64 * LD + 64 * LD) * 2)
__global__ __launch_bounds__(256) void qkv_kernel(
    const float* __restrict__ x,
    const float* __restrict__ Wq, const float* __restrict__ bq,
    const float* __restrict__ Wk, const float* __restrict__ bk,
    const float* __restrict__ Wv, const float* __restrict__ bv)
{
    extern __shared__ char sm[];
    __nv_bfloat16* Ah = (__nv_bfloat16*)sm;
    __nv_bfloat16* Al = Ah + 128 * LD;
    __nv_bfloat16* Bh = Al + 128 * LD;
    __nv_bfloat16* Bl = Bh + 64 * LD;
    const int tid = threadIdx.x, lane = tid & 31, wid = tid >> 5;
    const int wm = wid & 3, wn = wid >> 2;
    const int mb = blockIdx.x * 128;
    const int mat = blockIdx.y;
    const float* W  = (mat == 0) ? Wq : (mat == 1) ? Wk : Wv;
    const float* bp = (mat == 0) ? bq : (mat == 1) ? bk : bv;

    const uint32_t sAh = smem_u32(Ah), sAl = smem_u32(Al);
    const uint32_t sBh = smem_u32(Bh), sBl = smem_u32(Bl);
    const int lr = lane & 15, lc = (lane & 16) >> 1;
    const int br = (lane & 7) + ((lane & 16) >> 1), bc = lane & 8;

    float acc[2][4][4];
    #pragma unroll
    for (int m = 0; m < 2; m++)
        #pragma unroll
        for (int j = 0; j < 4; j++)
            #pragma unroll
            for (int e = 0; e < 4; e++) acc[m][j][e] = 0.0f;

    for (int ch = 0; ch < 16; ch++) {
        const int k0c = ch * 64;
        #pragma unroll
        for (int i = 0; i < 8; i++) {
            int idx = tid + i * 256;
            int row = idx >> 4, c4 = (idx & 15) * 4;
            float4 v = *(const float4*)(x + (size_t)(mb + row) * Cn + k0c + c4);
            __nv_bfloat16 h, l;
            split2(v.x, h, l); Ah[row * LD + c4]     = h; Al[row * LD + c4]     = l;
            split2(v.y, h, l); Ah[row * LD + c4 + 1] = h; Al[row * LD + c4 + 1] = l;
            split2(v.z, h, l); Ah[row * LD + c4 + 2] = h; Al[row * LD + c4 + 2] = l;
            split2(v.w, h, l); Ah[row * LD + c4 + 3] = h; Al[row * LD + c4 + 3] = l;
        }
        #pragma unroll
        for (int i = 0; i < 4; i++) {
            int idx = tid + i * 256;
            int k = idx >> 4, n4 = (idx & 15) * 4;
            float4 w = *(const float4*)(W + (size_t)(k0c + k) * Hn + n4);
            __nv_bfloat16 h, l;
            split2(w.x, h, l); Bh[(n4)     * LD + k] = h; Bl[(n4)     * LD + k] = l;
            split2(w.y, h, l); Bh[(n4 + 1) * LD + k] = h; Bl[(n4 + 1) * LD + k] = l;
            split2(w.z, h, l); Bh[(n4 + 2) * LD + k] = h; Bl[(n4 + 2) * LD + k] = l;
            split2(w.w, h, l); Bh[(n4 + 3) * LD + k] = h; Bl[(n4 + 3) * LD + k] = l;
        }
        __syncthreads();
        #pragma unroll
        for (int ks = 0; ks < 4; ks++) {
            const int k0 = ks * 16;
            uint32_t ah[2][4], al[2][4], bh[2][4], bl[2][4];
            #pragma unroll
            for (int m = 0; m < 2; m++) {
                uint32_t ra = (uint32_t)(((wm * 32 + m * 16 + lr) * LD + k0 + lc) * 2);
                ldsm_x4(ah[m][0], ah[m][1], ah[m][2], ah[m][3], sAh + ra);
                ldsm_x4(al[m][0], al[m][1], al[m][2], al[m][3], sAl + ra);
            }
            #pragma unroll
            for (int g = 0; g < 2; g++) {
                uint32_t rb = (uint32_t)(((wn * 32 + g * 16 + br) * LD + k0 + bc) * 2);
                ldsm_x4(bh[g][0], bh[g][1], bh[g][2], bh[g][3], sBh + rb);
                ldsm_x4(bl[g][0], bl[g][1], bl[g][2], bl[g][3], sBl + rb);
            }
            #pragma unroll
            for (int m = 0; m < 2; m++)
                #pragma unroll
                for (int j = 0; j < 4; j++) {
                    uint32_t b0h = bh[j >> 1][(j & 1) * 2], b1h = bh[j >> 1][(j & 1) * 2 + 1];
                    uint32_t b0l = bl[j >> 1][(j & 1) * 2], b1l = bl[j >> 1][(j & 1) * 2 + 1];
                    mma_bf16(acc[m][j], ah[m][0], ah[m][1], ah[m][2], ah[m][3], b0h, b1h);
                    mma_bf16(acc[m][j], al[m][0], al[m][1], al[m][2], al[m][3], b0h, b1h);
                    mma_bf16(acc[m][j], ah[m][0], ah[m][1], ah[m][2], ah[m][3], b0l, b1l);
                }
        }
        __syncthreads();
    }

    const int quad = lane >> 2, pair = lane & 3;
    const int b = mb >> 11, tloc0 = mb & 2047;
    if (mat < 2) {
        uint32_t* dh = (uint32_t*)(mat == 0 ? g_qh : g_kh);
        uint32_t* dl = (uint32_t*)(mat == 0 ? g_ql : g_kl);
        #pragma unroll
        for (int m = 0; m < 2; m++)
            #pragma unroll
            for (int rr = 0; rr < 2; rr++)
                #pragma unroll
                for (int j = 0; j < 4; j++) {
                    int row = wm * 32 + m * 16 + rr * 8 + quad;
                    int col = wn * 32 + j * 8 + 2 * pair;
                    float v0 = acc[m][j][rr * 2]     + bp[col];
                    float v1 = acc[m][j][rr * 2 + 1] + bp[col + 1];
                    __nv_bfloat16 h0, l0, h1, l1;
                    split2(v0, h0, l0); split2(v1, h1, l1);
                    size_t o = (size_t)(mb + row) * 32 + (col >> 1);
                    dh[o] = pack_bf2(h0, h1);
                    dl[o] = pack_bf2(l0, l1);
                }
    } else {
        __nv_bfloat16* Th = Ah;
        __nv_bfloat16* Tl = Al;
        #pragma unroll
        for (int m = 0; m < 2; m++)
            #pragma unroll
            for (int rr = 0; rr < 2; rr++)
                #pragma unroll
                for (int j = 0; j < 4; j++) {
                    int row = wm * 32 + m * 16 + rr * 8 + quad;
                    int col = wn * 32 + j * 8 + 2 * pair;
                    float v0 = acc[m][j][rr * 2]     + bp[col];
                    float v1 = acc[m][j][rr * 2 + 1] + bp[col + 1];
                    __nv_bfloat16 h, l;
                    split2(v0, h, l); Th[col * 132 + row] = h; Tl[col * 132 + row] = l;
                    split2(v1, h, l); Th[(col + 1) * 132 + row] = h; Tl[(col + 1) * 132 + row] = l;
                }
        __syncthreads();
        uint32_t* vh32 = (uint32_t*)g_vh;
        uint32_t* vl32 = (uint32_t*)g_vl;
        const uint32_t* th32 = (const uint32_t*)Th;
        const uint32_t* tl32 = (const uint32_t*)Tl;
        #pragma unroll
        for (int i = 0; i < 16; i++) {
            int idx = tid + i * 256;
            int d = idx >> 6, t2 = idx & 63;
            size_t o = (size_t)(b * 64 + d) * 1024 + (tloc0 >> 1) + t2;
            vh32[o] = th32[d * 66 + t2];
            vl32[o] = tl32[d * 66 + t2];
        }
    }
}

// ================= pass1: 64x128 S tile -> column sumexp z =================
// smem: Qh 0 (8K), Ql 8K, Kh 16K (16K), Kl 32K, zbuf 48K (1K)
#define P1_QH 0
#define P1_QL 8192
#define P1_KH 16384
#define P1_KL 32768
#define P1_ZB 49152
#define P1_SMEM (49152 + 1024)
__global__ __launch_bounds__(256, 2) void pass1_kernel()
{
    const int bt = blockIdx.x;            // 0..31 (64-row tiles)
    const int bs = blockIdx.y;            // 0..15 (128-col tiles)
    const int b  = blockIdx.z;
    const int bsMax = ((bt + 1) * 64 - 1) >> 7;
    if (bs > bsMax) return;

    extern __shared__ char sm[];
    const uint32_t sb = smem_u32(sm);
    const int tid = threadIdx.x, lane = tid & 31, wid = tid >> 5;
    const int wm = wid & 1, wn = wid >> 1;
    const int lr = lane & 15, lc = (lane & 16) >> 1;
    const int br = (lane & 7) + ((lane & 16) >> 1), bc = lane & 8;
    const int quad = lane >> 2, pair = lane & 3;

    {
        // Q tile: 64 rows x 64 bf16 = 512 uint4 (8 units/row)
        const uint4* qh = (const uint4*)(g_qh + ((size_t)b * Tn + bt * 64) * Hn);
        const uint4* ql = (const uint4*)(g_ql + ((size_t)b * Tn + bt * 64) * Hn);
        #pragma unroll
        for (int i = 0; i < 2; i++) {
            int idx = tid + i * 256;
            int row = idx >> 3, u = idx & 7;
            uint32_t off = SW128((uint32_t)(row * 128 + u * 16));
            *(uint4*)(sm + P1_QH + off) = qh[idx];
            *(uint4*)(sm + P1_QL + off) = ql[idx];
        }
        // K tile: 128 rows x 64 bf16 = 1024 uint4
        const uint4* kh = (const uint4*)(g_kh + ((size_t)b * Tn + bs * 128) * Hn);
        const uint4* kl = (const uint4*)(g_kl + ((size_t)b * Tn + bs * 128) * Hn);
        #pragma unroll
        for (int i = 0; i < 4; i++) {
            int idx = tid + i * 256;
            int row = idx >> 3, u = idx & 7;
            uint32_t off = SW128((uint32_t)(row * 128 + u * 16));
            *(uint4*)(sm + P1_KH + off) = kh[idx];
            *(uint4*)(sm + P1_KL + off) = kl[idx];
        }
    }
    __syncthreads();

    float acc[2][4][4];
    #pragma unroll
    for (int m = 0; m < 2; m++)
        #pragma unroll
        for (int j = 0; j < 4; j++)
            #pragma unroll
            for (int e = 0; e < 4; e++) acc[m][j][e] = 0.0f;

    #pragma unroll
    for (int ks = 0; ks < 4; ks++) {
        const int k0 = ks * 16;
        uint32_t ah[2][4], al[2][4], bh[2][4], bl[2][4];
        #pragma unroll
        for (int m = 0; m < 2; m++) {
            uint32_t ra = SW128((uint32_t)((wm * 32 + m * 16 + lr) * 128 + (k0 + lc) * 2));
            ldsm_x4(ah[m][0], ah[m][1], ah[m][2], ah[m][3], sb + P1_QH + ra);
            ldsm_x4(al[m][0], al[m][1], al[m][2], al[m][3], sb + P1_QL + ra);
        }
        #pragma unroll
        for (int g = 0; g < 2; g++) {
            uint32_t rb = SW128((uint32_t)((wn * 32 + g * 16 + br) * 128 + (k0 + bc) * 2));
            ldsm_x4(bh[g][0], bh[g][1], bh[g][2], bh[g][3], sb + P1_KH + rb);
            ldsm_x4(bl[g][0], bl[g][1], bl[g][2], bl[g][3], sb + P1_KL + rb);
        }
        #pragma unroll
        for (int m = 0; m < 2; m++)
            #pragma unroll
            for (int j = 0; j < 4; j++) {
                uint32_t b0h = bh[j >> 1][(j & 1) * 2], b1h = bh[j >> 1][(j & 1) * 2 + 1];
                uint32_t b0l = bl[j >> 1][(j & 1) * 2], b1l = bl[j >> 1][(j & 1) * 2 + 1];
                mma_bf16(acc[m][j], ah[m][0], ah[m][1], ah[m][2], ah[m][3], b0h, b1h);
                mma_bf16(acc[m][j], al[m][0], al[m][1], al[m][2], al[m][3], b0h, b1h);
                mma_bf16(acc[m][j], ah[m][0], ah[m][1], ah[m][2], ah[m][3], b0l, b1l);
            }
    }

    float* zbuf = (float*)(sm + P1_ZB);   // [2][128]
    #pragma unroll
    for (int j = 0; j < 4; j++) {
        float z0 = 0.0f, z1 = 0.0f;
        int cloc = wn * 32 + j * 8 + 2 * pair;
        int scol = bs * 128 + cloc;
        #pragma unroll
        for (int m = 0; m < 2; m++)
            #pragma unroll
            for (int rr = 0; rr < 2; rr++) {
                int trow = bt * 64 + wm * 32 + m * 16 + rr * 8 + quad;
                z0 += (scol     <= trow) ? fast_exp(acc[m][j][rr * 2])     : 0.0f;
                z1 += (scol + 1 <= trow) ? fast_exp(acc[m][j][rr * 2 + 1]) : 0.0f;
            }
        #pragma unroll
        for (int off = 4; off < 32; off <<= 1) {
            z0 += __shfl_xor_sync(0xffffffffu, z0, off);
            z1 += __shfl_xor_sync(0xffffffffu, z1, off);
        }
        if (quad == 0) {
            zbuf[wm * 128 + cloc]     = z0;
            zbuf[wm * 128 + cloc + 1] = z1;
        }
    }
    __syncthreads();
    if (tid < 128)
        g_z[((size_t)b * 32 + bt) * Tn + bs * 128 + tid] = zbuf[tid] + zbuf[128 + tid];
}

// ================= cmerge: sc[b][s] = 1 / sum_bt z =================
__global__ __launch_bounds__(256) void cmerge_kernel()
{
    int idx = blockIdx.x * 256 + threadIdx.x;
    int b = idx >> 11, s = idx & 2047;
    float z = 0.0f;
    for (int bt = s >> 6; bt < 32; bt++)
        z += g_z[((size_t)b * 32 + bt) * Tn + s];
    g_sc[idx] = 1.0f / z;
}

// ================= pass2: fused recompute + softmax + P@V^T, 64-row tiles =================
// smem: Qh 0(8K) Ql 8K | Kh 16K(16K) Kl 32K | Vh 48K(16K) Vl 64K | Ph 80K(16K) Pl 96K => 112 KB
#define P2_QH 0
#define P2_QL 8192
#define P2_KH 16384
#define P2_KL 32768
#define P2_VH 49152
#define P2_VL 65536
#define P2_PH 81920
#define P2_PL 98304
#define P2_SMEM 114688
__global__ __launch_bounds__(256, 2) void pass2_kernel(float* __restrict__ out)
{
    const int bt = 31 - blockIdx.x;       // longest first
    const int b  = blockIdx.y;
    const int bsMax = ((bt + 1) * 64 - 1) >> 7;

    extern __shared__ char sm[];
    const uint32_t sb = smem_u32(sm);
    const int tid = threadIdx.x, lane = tid & 31, wid = tid >> 5;
    const int wm = wid & 1, wn = wid >> 1;
    const int lr = lane & 15, lc = (lane & 16) >> 1;
    const int br = (lane & 7) + ((lane & 16) >> 1), bc = lane & 8;
    const int quad = lane >> 2, pair = lane & 3;

    // Q tile once: 64 rows x 64 bf16 = 512 uint4
    {
        const uint4* qh = (const uint4*)(g_qh + ((size_t)b * Tn + bt * 64) * Hn);
        const uint4* ql = (const uint4*)(g_ql + ((size_t)b * Tn + bt * 64) * Hn);
        #pragma unroll
        for (int i = 0; i < 2; i++) {
            int idx = tid + i * 256;
            int row = idx >> 3, u = idx & 7;
            uint32_t off = SW128((uint32_t)(row * 128 + u * 16));
            *(uint4*)(sm + P2_QH + off) = qh[idx];
            *(uint4*)(sm + P2_QL + off) = ql[idx];
        }
    }

    const uint4* gKh = (const uint4*)(g_kh + (size_t)b * Tn * Hn);
    const uint4* gKl = (const uint4*)(g_kl + (size_t)b * Tn * Hn);
    const uint4* gVh4 = (const uint4*)(g_vh + (size_t)b * Hn * Tn);
    const uint4* gVl4 = (const uint4*)(g_vl + (size_t)b * Hn * Tn);
    const float* scp = g_sc + b * Tn;

    float accO[2][2][4];
    #pragma unroll
    for (int m = 0; m < 2; m++)
        #pragma unroll
        for (int j = 0; j < 2; j++)
            #pragma unroll
            for (int e = 0; e < 4; e++) accO[m][j][e] = 0.0f;

    for (int bs = 0; bs <= bsMax; bs++) {
        __syncthreads();   // prev consumers of K/V done
        // K tile [128 s][64 k] = 1024 uint4
        #pragma unroll
        for (int i = 0; i < 4; i++) {
            int idx = tid + i * 256;
            int row = idx >> 3, u = idx & 7;
            uint32_t off = SW128((uint32_t)(row * 128 + u * 16));
            *(uint4*)(sm + P2_KH + off) = gKh[bs * 1024 + idx];
            *(uint4*)(sm + P2_KL + off) = gKl[bs * 1024 + idx];
        }
        // V^T tile [64 d][128 s] = 1024 uint4 (16 units/row of 256B)
        #pragma unroll
        for (int i = 0; i < 4; i++) {
            int idx = tid + i * 256;
            int d = idx >> 4, c = idx & 15;
            uint32_t off = SW256((uint32_t)(d * 256 + c * 16));
            *(uint4*)(sm + P2_VH + off) = gVh4[(size_t)d * 256 + bs * 16 + c];
            *(uint4*)(sm + P2_VL + off) = gVl4[(size_t)d * 256 + bs * 16 + c];
        }
        __syncthreads();

        // ---- S = Q K^T ----
        float acc[2][4][4];
        #pragma unroll
        for (int m = 0; m < 2; m++)
            #pragma unroll
            for (int j = 0; j < 4; j++)
                #pragma unroll
                for (int e = 0; e < 4; e++) acc[m][j][e] = 0.0f;
        #pragma unroll
        for (int ks = 0; ks < 4; ks++) {
            const int k0 = ks * 16;
            uint32_t ah[2][4], al[2][4], bh[2][4], bl[2][4];
            #pragma unroll
            for (int m = 0; m < 2; m++) {
                uint32_t ra = SW128((uint32_t)((wm * 32 + m * 16 + lr) * 128 + (k0 + lc) * 2));
                ldsm_x4(ah[m][0], ah[m][1], ah[m][2], ah[m][3], sb + P2_QH + ra);
                ldsm_x4(al[m][0], al[m][1], al[m][2], al[m][3], sb + P2_QL + ra);
            }
            #pragma unroll
            for (int g = 0; g < 2; g++) {
                uint32_t rb = SW128((uint32_t)((wn * 32 + g * 16 + br) * 128 + (k0 + bc) * 2));
                ldsm_x4(bh[g][0], bh[g][1], bh[g][2], bh[g][3], sb + P2_KH + rb);
                ldsm_x4(bl[g][0], bl[g][1], bl[g][2], bl[g][3], sb + P2_KL + rb);
            }
            #pragma unroll
            for (int m = 0; m < 2; m++)
                #pragma unroll
                for (int j = 0; j < 4; j++) {
                    uint32_t b0h = bh[j >> 1][(j & 1) * 2], b1h = bh[j >> 1][(j & 1) * 2 + 1];
                    uint32_t b0l = bl[j >> 1][(j & 1) * 2], b1l = bl[j >> 1][(j & 1) * 2 + 1];
                    mma_bf16(acc[m][j], ah[m][0], ah[m][1], ah[m][2], ah[m][3], b0h, b1h);
                    mma_bf16(acc[m][j], al[m][0], al[m][1], al[m][2], al[m][3], b0h, b1h);
                    mma_bf16(acc[m][j], ah[m][0], ah[m][1], ah[m][2], ah[m][3], b0l, b1l);
                }
        }

        // ---- P = exp(S) * sc -> smem (hi/lo) ----
        #pragma unroll
        for (int j = 0; j < 4; j++)
            #pragma unroll
            for (int m = 0; m < 2; m++)
                #pragma unroll
                for (int rr = 0; rr < 2; rr++) {
                    int rloc = wm * 32 + m * 16 + rr * 8 + quad;
                    int cloc = wn * 32 + j * 8 + 2 * pair;
                    int trow = bt * 64 + rloc;
                    int scol = bs * 128 + cloc;
                    float p0 = (scol     <= trow) ? fast_exp(acc[m][j][rr * 2])     * __ldg(scp + scol)     : 0.0f;
                    float p1 = (scol + 1 <= trow) ? fast_exp(acc[m][j][rr * 2 + 1]) * __ldg(scp + scol + 1) : 0.0f;
                    __nv_bfloat16 h0, l0, h1, l1;
                    split2(p0, h0, l0); split2(p1, h1, l1);
                    uint32_t off = SW256((uint32_t)(rloc * 256 + cloc * 2));
                    *(uint32_t*)(sm + P2_PH + off) = pack_bf2(h0, h1);
                    *(uint32_t*)(sm + P2_PL + off) = pack_bf2(l0, l1);
                }
        __syncthreads();

        // ---- O += P @ V^T ----
        #pragma unroll
        for (int ks = 0; ks < 8; ks++) {
            const int k0 = ks * 16;
            uint32_t ah[2][4], al[2][4], bh[4], blr[4];
            #pragma unroll
            for (int m = 0; m < 2; m++) {
                uint32_t ra = SW256((uint32_t)((wm * 32 + m * 16 + lr) * 256 + (k0 + lc) * 2));
                ldsm_x4(ah[m][0], ah[m][1], ah[m][2], ah[m][3], sb + P2_PH + ra);
                ldsm_x4(al[m][0], al[m][1], al[m][2], al[m][3], sb + P2_PL + ra);
            }
            {
                uint32_t rb = SW256((uint32_t)((wn * 16 + br) * 256 + (k0 + bc) * 2));
                ldsm_x4(bh[0], bh[1], bh[2], bh[3], sb + P2_VH + rb);
                ldsm_x4(blr[0], blr[1], blr[2], blr[3], sb + P2_VL + rb);
            }
            #pragma unroll
            for (int m = 0; m < 2; m++)
                #pragma unroll
                for (int j = 0; j < 2; j++) {
                    uint32_t b0h = bh[j * 2], b1h = bh[j * 2 + 1];
                    uint32_t b0l = blr[j * 2], b1l = blr[j * 2 + 1];
                    mma_bf16(accO[m][j], ah[m][0], ah[m][1], ah[m][2], ah[m][3], b0h, b1h);
                    mma_bf16(accO[m][j], al[m][0], al[m][1], al[m][2], al[m][3], b0h, b1h);
                    mma_bf16(accO[m][j], ah[m][0], ah[m][1], ah[m][2], ah[m][3], b0l, b1l);
                }
        }
    }

    #pragma unroll
    for (int m = 0; m < 2; m++)
        #pragma unroll
        for (int rr = 0; rr < 2; rr++)
            #pragma unroll
            for (int j = 0; j < 2; j++) {
                int row = bt * 64 + wm * 32 + m * 16 + rr * 8 + quad;
                int col = wn * 16 + j * 8 + 2 * pair;
                float2 v = make_float2(accO[m][j][rr * 2], accO[m][j][rr * 2 + 1]);
                *(float2*)(out + ((size_t)b * Tn + row) * Hn + col) = v;
            }
}

extern "C" void kernel_launch(void* const* d_in, const int* in_sizes, int n_in,
                              void* d_out, int out_size)
{
    const float* x  = (const float*)d_in[0];
    const float* Wq = (const float*)d_in[1];
    const float* bq = (const float*)d_in[2];
    const float* Wk = (const float*)d_in[3];
    const float* bk = (const float*)d_in[4];
    const float* Wv = (const float*)d_in[5];
    const float* bv = (const float*)d_in[6];
    float* out = (float*)d_out;

    cudaFuncSetAttribute(qkv_kernel,   cudaFuncAttributeMaxDynamicSharedMemorySize, QK_SMEM);
    cudaFuncSetAttribute(pass1_kernel, cudaFuncAttributeMaxDynamicSharedMemorySize, P1_SMEM);
    cudaFuncSetAttribute(pass2_kernel, cudaFuncAttributeMaxDynamicSharedMemorySize, P2_SMEM);

    qkv_kernel<<<dim3(256, 3), 256, QK_SMEM>>>(x, Wq, bq, Wk, bk, Wv, bv);
    pass1_kernel<<<dim3(32, 16, 16), 256, P1_SMEM>>>();
    cmerge_kernel<<<128, 256>>>();
    pass2_kernel<<<dim3(32, 16), 256, P2_SMEM>>>(out);
}

// round 8
// speedup vs baseline: 1.1064x; 1.0177x over previous
#include <cuda_runtime.h>
#include <cuda_bf16.h>
#include <cstdint>

#define Bn 16
#define Tn 2048
#define Cn 1024
#define Hn 64
#define LD 72          // padded stride used only by qkv kernel

// ---------------- static scratch ----------------
__device__ __nv_bfloat16 g_qh[(size_t)Bn * Tn * Hn];
__device__ __nv_bfloat16 g_ql[(size_t)Bn * Tn * Hn];
__device__ __nv_bfloat16 g_kh[(size_t)Bn * Tn * Hn];
__device__ __nv_bfloat16 g_kl[(size_t)Bn * Tn * Hn];
__device__ __nv_bfloat16 g_vh[(size_t)Bn * Hn * Tn];   // transposed [b][d][t]
__device__ __nv_bfloat16 g_vl[(size_t)Bn * Hn * Tn];
__device__ __nv_bfloat16 g_v2h[(size_t)Bn * Hn * Tn];  // v' = sc * v
__device__ __nv_bfloat16 g_v2l[(size_t)Bn * Hn * Tn];
__device__ float g_z[(size_t)Bn * 32 * Tn];            // per-(b, 64-row tile) column sumexp
__device__ float g_sc[Bn * Tn];                        // 1 / sum z

// ---------------- helpers ----------------
__device__ __forceinline__ uint32_t smem_u32(const void* p) {
    uint32_t a;
    asm("{ .reg .u64 t; cvta.to.shared.u64 t, %1; cvt.u32.u64 %0, t; }" : "=r"(a) : "l"(p));
    return a;
}
__device__ __forceinline__ void ldsm_x4(uint32_t& r0, uint32_t& r1, uint32_t& r2, uint32_t& r3, uint32_t a) {
    asm volatile("ldmatrix.sync.aligned.m8n8.x4.shared.b16 {%0,%1,%2,%3}, [%4];"
                 : "=r"(r0), "=r"(r1), "=r"(r2), "=r"(r3) : "r"(a));
}
__device__ __forceinline__ void mma_bf16(float* c, uint32_t a0, uint32_t a1, uint32_t a2, uint32_t a3,
                                         uint32_t b0, uint32_t b1) {
    asm volatile("mma.sync.aligned.m16n8k16.row.col.f32.bf16.bf16.f32 "
                 "{%0,%1,%2,%3},{%4,%5,%6,%7},{%8,%9},{%0,%1,%2,%3};"
                 : "+f"(c[0]), "+f"(c[1]), "+f"(c[2]), "+f"(c[3])
                 : "r"(a0), "r"(a1), "r"(a2), "r"(a3), "r"(b0), "r"(b1));
}
__device__ __forceinline__ uint32_t pack_bf2(__nv_bfloat16 a, __nv_bfloat16 b) {
    unsigned short ua = *reinterpret_cast<unsigned short*>(&a);
    unsigned short ub = *reinterpret_cast<unsigned short*>(&b);
    return ((uint32_t)ub << 16) | ua;
}
__device__ __forceinline__ float fast_exp(float x) {
    float y = fmaxf(x * 1.4426950408889634f, -126.0f);
    float z = y + 12582912.0f;
    int   i = __float_as_int(z) - 0x4B400000;
    float f = y - (z - 12582912.0f);
    float p = 1.3333558146428443e-3f;
    p = fmaf(p, f, 9.618129107628477e-3f);
    p = fmaf(p, f, 5.550410866482158e-2f);
    p = fmaf(p, f, 2.402265069591007e-1f);
    p = fmaf(p, f, 6.931471805599453e-1f);
    p = fmaf(p, f, 1.0f);
    return __int_as_float(__float_as_int(p) + (i << 23));
}
__device__ __forceinline__ void split2(float v, __nv_bfloat16& h, __nv_bfloat16& l) {
    h = __float2bfloat16(v);
    l = __float2bfloat16(v - __bfloat162float(h));
}
// XOR swizzles (16B-unit granularity)
#define SW128(o) ((o) ^ (((o) >> 3) & 0x70))   // 128B rows
#define SW256(o) ((o) ^ (((o) >> 4) & 0x70))   // 256B rows

// ================= K1: QKV projection =================
// 1-D grid: bid = rowblk*3 + mat, so the 3 mats of one x row-block are
// launch-adjacent -> x re-reads hit L2.
#define QK_SMEM ((128 * LD + 128 * LD + 64 * LD + 64 * LD) * 2)
__global__ __launch_bounds__(256, 2) void qkv_kernel(
    const float* __restrict__ x,
    const float* __restrict__ Wq, const float* __restrict__ bq,
    const float* __restrict__ Wk, const float* __restrict__ bk,
    const float* __restrict__ Wv, const float* __restrict__ bv)
{
    extern __shared__ char sm[];
    __nv_bfloat16* Ah = (__nv_bfloat16*)sm;
    __nv_bfloat16* Al = Ah + 128 * LD;
    __nv_bfloat16* Bh = Al + 128 * LD;
    __nv_bfloat16* Bl = Bh + 64 * LD;
    const int tid = threadIdx.x, lane = tid & 31, wid = tid >> 5;
    const int wm = wid & 3, wn = wid >> 2;
    const int bid = blockIdx.x;
    const int mat = bid % 3;
    const int mb = (bid / 3) * 128;
    const float* W  = (mat == 0) ? Wq : (mat == 1) ? Wk : Wv;
    const float* bp = (mat == 0) ? bq : (mat == 1) ? bk : bv;

    const uint32_t sAh = smem_u32(Ah), sAl = smem_u32(Al);
    const uint32_t sBh = smem_u32(Bh), sBl = smem_u32(Bl);
    const int lr = lane & 15, lc = (lane & 16) >> 1;
    const int br = (lane & 7) + ((lane & 16) >> 1), bc = lane & 8;

    float acc[2][4][4];
    #pragma unroll
    for (int m = 0; m < 2; m++)
        #pragma unroll
        for (int j = 0; j < 4; j++)
            #pragma unroll
            for (int e = 0; e < 4; e++) acc[m][j][e] = 0.0f;

    for (int ch = 0; ch < 16; ch++) {
        const int k0c = ch * 64;
        #pragma unroll
        for (int i = 0; i < 8; i++) {
            int idx = tid + i * 256;
            int row = idx >> 4, c4 = (idx & 15) * 4;
            float4 v = *(const float4*)(x + (size_t)(mb + row) * Cn + k0c + c4);
            __nv_bfloat16 h, l;
            split2(v.x, h, l); Ah[row * LD + c4]     = h; Al[row * LD + c4]     = l;
            split2(v.y, h, l); Ah[row * LD + c4 + 1] = h; Al[row * LD + c4 + 1] = l;
            split2(v.z, h, l); Ah[row * LD + c4 + 2] = h; Al[row * LD + c4 + 2] = l;
            split2(v.w, h, l); Ah[row * LD + c4 + 3] = h; Al[row * LD + c4 + 3] = l;
        }
        #pragma unroll
        for (int i = 0; i < 4; i++) {
            int idx = tid + i * 256;
            int k = idx >> 4, n4 = (idx & 15) * 4;
            float4 w = *(const float4*)(W + (size_t)(k0c + k) * Hn + n4);
            __nv_bfloat16 h, l;
            split2(w.x, h, l); Bh[(n4)     * LD + k] = h; Bl[(n4)     * LD + k] = l;
            split2(w.y, h, l); Bh[(n4 + 1) * LD + k] = h; Bl[(n4 + 1) * LD + k] = l;
            split2(w.z, h, l); Bh[(n4 + 2) * LD + k] = h; Bl[(n4 + 2) * LD + k] = l;
            split2(w.w, h, l); Bh[(n4 + 3) * LD + k] = h; Bl[(n4 + 3) * LD + k] = l;
        }
        __syncthreads();
        #pragma unroll
        for (int ks = 0; ks < 4; ks++) {
            const int k0 = ks * 16;
            uint32_t ah[2][4], al[2][4], bh[2][4], bl[2][4];
            #pragma unroll
            for (int m = 0; m < 2; m++) {
                uint32_t ra = (uint32_t)(((wm * 32 + m * 16 + lr) * LD + k0 + lc) * 2);
                ldsm_x4(ah[m][0], ah[m][1], ah[m][2], ah[m][3], sAh + ra);
                ldsm_x4(al[m][0], al[m][1], al[m][2], al[m][3], sAl + ra);
            }
            #pragma unroll
            for (int g = 0; g < 2; g++) {
                uint32_t rb = (uint32_t)(((wn * 32 + g * 16 + br) * LD + k0 + bc) * 2);
                ldsm_x4(bh[g][0], bh[g][1], bh[g][2], bh[g][3], sBh + rb);
                ldsm_x4(bl[g][0], bl[g][1], bl[g][2], bl[g][3], sBl + rb);
            }
            #pragma unroll
            for (int m = 0; m < 2; m++)
                #pragma unroll
                for (int j = 0; j < 4; j++) {
                    uint32_t b0h = bh[j >> 1][(j & 1) * 2], b1h = bh[j >> 1][(j & 1) * 2 + 1];
                    uint32_t b0l = bl[j >> 1][(j & 1) * 2], b1l = bl[j >> 1][(j & 1) * 2 + 1];
                    mma_bf16(acc[m][j], ah[m][0], ah[m][1], ah[m][2], ah[m][3], b0h, b1h);
                    mma_bf16(acc[m][j], al[m][0], al[m][1], al[m][2], al[m][3], b0h, b1h);
                    mma_bf16(acc[m][j], ah[m][0], ah[m][1], ah[m][2], ah[m][3], b0l, b1l);
                }
        }
        __syncthreads();
    }

    const int quad = lane >> 2, pair = lane & 3;
    const int b = mb >> 11, tloc0 = mb & 2047;
    if (mat < 2) {
        uint32_t* dh = (uint32_t*)(mat == 0 ? g_qh : g_kh);
        uint32_t* dl = (uint32_t*)(mat == 0 ? g_ql : g_kl);
        #pragma unroll
        for (int m = 0; m < 2; m++)
            #pragma unroll
            for (int rr = 0; rr < 2; rr++)
                #pragma unroll
                for (int j = 0; j < 4; j++) {
                    int row = wm * 32 + m * 16 + rr * 8 + quad;
                    int col = wn * 32 + j * 8 + 2 * pair;
                    float v0 = acc[m][j][rr * 2]     + bp[col];
                    float v1 = acc[m][j][rr * 2 + 1] + bp[col + 1];
                    __nv_bfloat16 h0, l0, h1, l1;
                    split2(v0, h0, l0); split2(v1, h1, l1);
                    size_t o = (size_t)(mb + row) * 32 + (col >> 1);
                    dh[o] = pack_bf2(h0, h1);
                    dl[o] = pack_bf2(l0, l1);
                }
    } else {
        __nv_bfloat16* Th = Ah;
        __nv_bfloat16* Tl = Al;
        #pragma unroll
        for (int m = 0; m < 2; m++)
            #pragma unroll
            for (int rr = 0; rr < 2; rr++)
                #pragma unroll
                for (int j = 0; j < 4; j++) {
                    int row = wm * 32 + m * 16 + rr * 8 + quad;
                    int col = wn * 32 + j * 8 + 2 * pair;
                    float v0 = acc[m][j][rr * 2]     + bp[col];
                    float v1 = acc[m][j][rr * 2 + 1] + bp[col + 1];
                    __nv_bfloat16 h, l;
                    split2(v0, h, l); Th[col * 132 + row] = h; Tl[col * 132 + row] = l;
                    split2(v1, h, l); Th[(col + 1) * 132 + row] = h; Tl[(col + 1) * 132 + row] = l;
                }
        __syncthreads();
        uint32_t* vh32 = (uint32_t*)g_vh;
        uint32_t* vl32 = (uint32_t*)g_vl;
        const uint32_t* th32 = (const uint32_t*)Th;
        const uint32_t* tl32 = (const uint32_t*)Tl;
        #pragma unroll
        for (int i = 0; i < 16; i++) {
            int idx = tid + i * 256;
            int d = idx >> 6, t2 = idx & 63;
            size_t o = (size_t)(b * 64 + d) * 1024 + (tloc0 >> 1) + t2;
            vh32[o] = th32[d * 66 + t2];
            vl32[o] = tl32[d * 66 + t2];
        }
    }
}

// ================= pass1: 64x128 S tile -> column sumexp z =================
#define P1_QH 0
#define P1_QL 8192
#define P1_KH 16384
#define P1_KL 32768
#define P1_ZB 49152
#define P1_SMEM (49152 + 1024)
__global__ __launch_bounds__(256, 2) void pass1_kernel()
{
    const int bt = blockIdx.x;            // 0..31 (64-row tiles)
    const int bs = blockIdx.y;            // 0..15 (128-col tiles)
    const int b  = blockIdx.z;
    const int bsMax = ((bt + 1) * 64 - 1) >> 7;
    if (bs > bsMax) return;

    extern __shared__ char sm[];
    const uint32_t sb = smem_u32(sm);
    const int tid = threadIdx.x, lane = tid & 31, wid = tid >> 5;
    const int wm = wid & 1, wn = wid >> 1;
    const int lr = lane & 15, lc = (lane & 16) >> 1;
    const int br = (lane & 7) + ((lane & 16) >> 1), bc = lane & 8;
    const int quad = lane >> 2, pair = lane & 3;

    {
        const uint4* qh = (const uint4*)(g_qh + ((size_t)b * Tn + bt * 64) * Hn);
        const uint4* ql = (const uint4*)(g_ql + ((size_t)b * Tn + bt * 64) * Hn);
        #pragma unroll
        for (int i = 0; i < 2; i++) {
            int idx = tid + i * 256;
            int row = idx >> 3, u = idx & 7;
            uint32_t off = SW128((uint32_t)(row * 128 + u * 16));
            *(uint4*)(sm + P1_QH + off) = qh[idx];
            *(uint4*)(sm + P1_QL + off) = ql[idx];
        }
        const uint4* kh = (const uint4*)(g_kh + ((size_t)b * Tn + bs * 128) * Hn);
        const uint4* kl = (const uint4*)(g_kl + ((size_t)b * Tn + bs * 128) * Hn);
        #pragma unroll
        for (int i = 0; i < 4; i++) {
            int idx = tid + i * 256;
            int row = idx >> 3, u = idx & 7;
            uint32_t off = SW128((uint32_t)(row * 128 + u * 16));
            *(uint4*)(sm + P1_KH + off) = kh[idx];
            *(uint4*)(sm + P1_KL + off) = kl[idx];
        }
    }
    __syncthreads();

    float acc[2][4][4];
    #pragma unroll
    for (int m = 0; m < 2; m++)
        #pragma unroll
        for (int j = 0; j < 4; j++)
            #pragma unroll
            for (int e = 0; e < 4; e++) acc[m][j][e] = 0.0f;

    #pragma unroll
    for (int ks = 0; ks < 4; ks++) {
        const int k0 = ks * 16;
        uint32_t ah[2][4], al[2][4], bh[2][4], bl[2][4];
        #pragma unroll
        for (int m = 0; m < 2; m++) {
            uint32_t ra = SW128((uint32_t)((wm * 32 + m * 16 + lr) * 128 + (k0 + lc) * 2));
            ldsm_x4(ah[m][0], ah[m][1], ah[m][2], ah[m][3], sb + P1_QH + ra);
            ldsm_x4(al[m][0], al[m][1], al[m][2], al[m][3], sb + P1_QL + ra);
        }
        #pragma unroll
        for (int g = 0; g < 2; g++) {
            uint32_t rb = SW128((uint32_t)((wn * 32 + g * 16 + br) * 128 + (k0 + bc) * 2));
            ldsm_x4(bh[g][0], bh[g][1], bh[g][2], bh[g][3], sb + P1_KH + rb);
            ldsm_x4(bl[g][0], bl[g][1], bl[g][2], bl[g][3], sb + P1_KL + rb);
        }
        #pragma unroll
        for (int m = 0; m < 2; m++)
            #pragma unroll
            for (int j = 0; j < 4; j++) {
                uint32_t b0h = bh[j >> 1][(j & 1) * 2], b1h = bh[j >> 1][(j & 1) * 2 + 1];
                uint32_t b0l = bl[j >> 1][(j & 1) * 2], b1l = bl[j >> 1][(j & 1) * 2 + 1];
                mma_bf16(acc[m][j], ah[m][0], ah[m][1], ah[m][2], ah[m][3], b0h, b1h);
                mma_bf16(acc[m][j], al[m][0], al[m][1], al[m][2], al[m][3], b0h, b1h);
                mma_bf16(acc[m][j], ah[m][0], ah[m][1], ah[m][2], ah[m][3], b0l, b1l);
            }
    }

    float* zbuf = (float*)(sm + P1_ZB);   // [2][128]
    #pragma unroll
    for (int j = 0; j < 4; j++) {
        float z0 = 0.0f, z1 = 0.0f;
        int cloc = wn * 32 + j * 8 + 2 * pair;
        int scol = bs * 128 + cloc;
        #pragma unroll
        for (int m = 0; m < 2; m++)
            #pragma unroll
            for (int rr = 0; rr < 2; rr++) {
                int trow = bt * 64 + wm * 32 + m * 16 + rr * 8 + quad;
                z0 += (scol     <= trow) ? fast_exp(acc[m][j][rr * 2])     : 0.0f;
                z1 += (scol + 1 <= trow) ? fast_exp(acc[m][j][rr * 2 + 1]) : 0.0f;
            }
        #pragma unroll
        for (int off = 4; off < 32; off <<= 1) {
            z0 += __shfl_xor_sync(0xffffffffu, z0, off);
            z1 += __shfl_xor_sync(0xffffffffu, z1, off);
        }
        if (quad == 0) {
            zbuf[wm * 128 + cloc]     = z0;
            zbuf[wm * 128 + cloc + 1] = z1;
        }
    }
    __syncthreads();
    if (tid < 128)
        g_z[((size_t)b * 32 + bt) * Tn + bs * 128 + tid] = zbuf[tid] + zbuf[128 + tid];
}

// ================= cmerge: sc[b][s] = 1 / sum_bt z =================
__global__ __launch_bounds__(256) void cmerge_kernel()
{
    int idx = blockIdx.x * 256 + threadIdx.x;
    int b = idx >> 11, s = idx & 2047;
    float z = 0.0f;
    for (int bt = s >> 6; bt < 32; bt++)
        z += g_z[((size_t)b * 32 + bt) * Tn + s];
    g_sc[idx] = 1.0f / z;
}

// ================= vscale: v' = sc[t] * v (per [b][d][t]) =================
__global__ __launch_bounds__(256) void vscale_kernel()
{
    int idx = blockIdx.x * 256 + threadIdx.x;   // u32 index over Bn*Hn*Tn/2
    int t2 = idx & 1023;                        // t-pair
    int b  = idx >> 16;                         // (idx >> 10) >> 6
    uint32_t hw = ((const uint32_t*)g_vh)[idx];
    uint32_t lw = ((const uint32_t*)g_vl)[idx];
    __nv_bfloat162 hb = *(__nv_bfloat162*)&hw;
    __nv_bfloat162 lb = *(__nv_bfloat162*)&lw;
    float sc0 = g_sc[b * Tn + 2 * t2];
    float sc1 = g_sc[b * Tn + 2 * t2 + 1];
    float v0 = (__low2float(hb)  + __low2float(lb))  * sc0;
    float v1 = (__high2float(hb) + __high2float(lb)) * sc1;
    __nv_bfloat16 h0, l0, h1, l1;
    split2(v0, h0, l0); split2(v1, h1, l1);
    ((uint32_t*)g_v2h)[idx] = pack_bf2(h0, h1);
    ((uint32_t*)g_v2l)[idx] = pack_bf2(l0, l1);
}

// ================= pass2: fused recompute + exp + P@V'^T, 64-row tiles =================
#define P2_QH 0
#define P2_QL 8192
#define P2_KH 16384
#define P2_KL 32768
#define P2_VH 49152
#define P2_VL 65536
#define P2_PH 81920
#define P2_PL 98304
#define P2_SMEM 114688
__global__ __launch_bounds__(256, 2) void pass2_kernel(float* __restrict__ out)
{
    const int bt = 31 - blockIdx.x;       // longest first
    const int b  = blockIdx.y;
    const int bsMax = ((bt + 1) * 64 - 1) >> 7;

    extern __shared__ char sm[];
    const uint32_t sb = smem_u32(sm);
    const int tid = threadIdx.x, lane = tid & 31, wid = tid >> 5;
    const int wm = wid & 1, wn = wid >> 1;
    const int lr = lane & 15, lc = (lane & 16) >> 1;
    const int br = (lane & 7) + ((lane & 16) >> 1), bc = lane & 8;
    const int quad = lane >> 2, pair = lane & 3;

    // Q tile once: 64 rows x 64 bf16 = 512 uint4
    {
        const uint4* qh = (const uint4*)(g_qh + ((size_t)b * Tn + bt * 64) * Hn);
        const uint4* ql = (const uint4*)(g_ql + ((size_t)b * Tn + bt * 64) * Hn);
        #pragma unroll
        for (int i = 0; i < 2; i++) {
            int idx = tid + i * 256;
            int row = idx >> 3, u = idx & 7;
            uint32_t off = SW128((uint32_t)(row * 128 + u * 16));
            *(uint4*)(sm + P2_QH + off) = qh[idx];
            *(uint4*)(sm + P2_QL + off) = ql[idx];
        }
    }

    const uint4* gKh = (const uint4*)(g_kh + (size_t)b * Tn * Hn);
    const uint4* gKl = (const uint4*)(g_kl + (size_t)b * Tn * Hn);
    const uint4* gVh4 = (const uint4*)(g_v2h + (size_t)b * Hn * Tn);
    const uint4* gVl4 = (const uint4*)(g_v2l + (size_t)b * Hn * Tn);

    float accO[2][2][4];
    #pragma unroll
    for (int m = 0; m < 2; m++)
        #pragma unroll
        for (int j = 0; j < 2; j++)
            #pragma unroll
            for (int e = 0; e < 4; e++) accO[m][j][e] = 0.0f;

    for (int bs = 0; bs <= bsMax; bs++) {
        __syncthreads();   // prev consumers of K/V done
        // K tile [128 s][64 k] = 1024 uint4
        #pragma unroll
        for (int i = 0; i < 4; i++) {
            int idx = tid + i * 256;
            int row = idx >> 3, u = idx & 7;
            uint32_t off = SW128((uint32_t)(row * 128 + u * 16));
            *(uint4*)(sm + P2_KH + off) = gKh[bs * 1024 + idx];
            *(uint4*)(sm + P2_KL + off) = gKl[bs * 1024 + idx];
        }
        // V'^T tile [64 d][128 s] = 1024 uint4
        #pragma unroll
        for (int i = 0; i < 4; i++) {
            int idx = tid + i * 256;
            int d = idx >> 4, c = idx & 15;
            uint32_t off = SW256((uint32_t)(d * 256 + c * 16));
            *(uint4*)(sm + P2_VH + off) = gVh4[(size_t)d * 256 + bs * 16 + c];
            *(uint4*)(sm + P2_VL + off) = gVl4[(size_t)d * 256 + bs * 16 + c];
        }
        __syncthreads();

        // ---- S = Q K^T ----
        float acc[2][4][4];
        #pragma unroll
        for (int m = 0; m < 2; m++)
            #pragma unroll
            for (int j = 0; j < 4; j++)
                #pragma unroll
                for (int e = 0; e < 4; e++) acc[m][j][e] = 0.0f;
        #pragma unroll
        for (int ks = 0; ks < 4; ks++) {
            const int k0 = ks * 16;
            uint32_t ah[2][4], al[2][4], bh[2][4], bl[2][4];
            #pragma unroll
            for (int m = 0; m < 2; m++) {
                uint32_t ra = SW128((uint32_t)((wm * 32 + m * 16 + lr) * 128 + (k0 + lc) * 2));
                ldsm_x4(ah[m][0], ah[m][1], ah[m][2], ah[m][3], sb + P2_QH + ra);
                ldsm_x4(al[m][0], al[m][1], al[m][2], al[m][3], sb + P2_QL + ra);
            }
            #pragma unroll
            for (int g = 0; g < 2; g++) {
                uint32_t rb = SW128((uint32_t)((wn * 32 + g * 16 + br) * 128 + (k0 + bc) * 2));
                ldsm_x4(bh[g][0], bh[g][1], bh[g][2], bh[g][3], sb + P2_KH + rb);
                ldsm_x4(bl[g][0], bl[g][1], bl[g][2], bl[g][3], sb + P2_KL + rb);
            }
            #pragma unroll
            for (int m = 0; m < 2; m++)
                #pragma unroll
                for (int j = 0; j < 4; j++) {
                    uint32_t b0h = bh[j >> 1][(j & 1) * 2], b1h = bh[j >> 1][(j & 1) * 2 + 1];
                    uint32_t b0l = bl[j >> 1][(j & 1) * 2], b1l = bl[j >> 1][(j & 1) * 2 + 1];
                    mma_bf16(acc[m][j], ah[m][0], ah[m][1], ah[m][2], ah[m][3], b0h, b1h);
                    mma_bf16(acc[m][j], al[m][0], al[m][1], al[m][2], al[m][3], b0h, b1h);
                    mma_bf16(acc[m][j], ah[m][0], ah[m][1], ah[m][2], ah[m][3], b0l, b1l);
                }
        }

        // ---- P = exp(S) (masked) -> smem (hi/lo); sc already folded into V' ----
        #pragma unroll
        for (int j = 0; j < 4; j++)
            #pragma unroll
            for (int m = 0; m < 2; m++)
                #pragma unroll
                for (int rr = 0; rr < 2; rr++) {
                    int rloc = wm * 32 + m * 16 + rr * 8 + quad;
                    int cloc = wn * 32 + j * 8 + 2 * pair;
                    int trow = bt * 64 + rloc;
                    int scol = bs * 128 + cloc;
                    float p0 = (scol     <= trow) ? fast_exp(acc[m][j][rr * 2])     : 0.0f;
                    float p1 = (scol + 1 <= trow) ? fast_exp(acc[m][j][rr * 2 + 1]) : 0.0f;
                    __nv_bfloat16 h0, l0, h1, l1;
                    split2(p0, h0, l0); split2(p1, h1, l1);
                    uint32_t off = SW256((uint32_t)(rloc * 256 + cloc * 2));
                    *(uint32_t*)(sm + P2_PH + off) = pack_bf2(h0, h1);
                    *(uint32_t*)(sm + P2_PL + off) = pack_bf2(l0, l1);
                }
        __syncthreads();

        // ---- O += P @ V'^T ----
        #pragma unroll
        for (int ks = 0; ks < 8; ks++) {
            const int k0 = ks * 16;
            uint32_t ah[2][4], al[2][4], bh[4], blr[4];
            #pragma unroll
            for (int m = 0; m < 2; m++) {
                uint32_t ra = SW256((uint32_t)((wm * 32 + m * 16 + lr) * 256 + (k0 + lc) * 2));
                ldsm_x4(ah[m][0], ah[m][1], ah[m][2], ah[m][3], sb + P2_PH + ra);
                ldsm_x4(al[m][0], al[m][1], al[m][2], al[m][3], sb + P2_PL + ra);
            }
            {
                uint32_t rb = SW256((uint32_t)((wn * 16 + br) * 256 + (k0 + bc) * 2));
                ldsm_x4(bh[0], bh[1], bh[2], bh[3], sb + P2_VH + rb);
                ldsm_x4(blr[0], blr[1], blr[2], blr[3], sb + P2_VL + rb);
            }
            #pragma unroll
            for (int m = 0; m < 2; m++)
                #pragma unroll
                for (int j = 0; j < 2; j++) {
                    uint32_t b0h = bh[j * 2], b1h = bh[j * 2 + 1];
                    uint32_t b0l = blr[j * 2], b1l = blr[j * 2 + 1];
                    mma_bf16(accO[m][j], ah[m][0], ah[m][1], ah[m][2], ah[m][3], b0h, b1h);
                    mma_bf16(accO[m][j], al[m][0], al[m][1], al[m][2], al[m][3], b0h, b1h);
                    mma_bf16(accO[m][j], ah[m][0], ah[m][1], ah[m][2], ah[m][3], b0l, b1l);
                }
        }
    }

    #pragma unroll
    for (int m = 0; m < 2; m++)
        #pragma unroll
        for (int rr = 0; rr < 2; rr++)
            #pragma unroll
            for (int j = 0; j < 2; j++) {
                int row = bt * 64 + wm * 32 + m * 16 + rr * 8 + quad;
                int col = wn * 16 + j * 8 + 2 * pair;
                float2 v = make_float2(accO[m][j][rr * 2], accO[m][j][rr * 2 + 1]);
                *(float2*)(out + ((size_t)b * Tn + row) * Hn + col) = v;
            }
}

extern "C" void kernel_launch(void* const* d_in, const int* in_sizes, int n_in,
                              void* d_out, int out_size)
{
    const float* x  = (const float*)d_in[0];
    const float* Wq = (const float*)d_in[1];
    const float* bq = (const float*)d_in[2];
    const float* Wk = (const float*)d_in[3];
    const float* bk = (const float*)d_in[4];
    const float* Wv = (const float*)d_in[5];
    const float* bv = (const float*)d_in[6];
    float* out = (float*)d_out;

    cudaFuncSetAttribute(qkv_kernel,   cudaFuncAttributeMaxDynamicSharedMemorySize, QK_SMEM);
    cudaFuncSetAttribute(pass1_kernel, cudaFuncAttributeMaxDynamicSharedMemorySize, P1_SMEM);
    cudaFuncSetAttribute(pass2_kernel, cudaFuncAttributeMaxDynamicSharedMemorySize, P2_SMEM);

    qkv_kernel<<<768, 256, QK_SMEM>>>(x, Wq, bq, Wk, bk, Wv, bv);
    pass1_kernel<<<dim3(32, 16, 16), 256, P1_SMEM>>>();
    cmerge_kernel<<<128, 256>>>();
    vscale_kernel<<<4096, 256>>>();
    pass2_kernel<<<dim3(32, 16), 256, P2_SMEM>>>(out);
}